// round 9
// baseline (speedup 1.0000x reference)
#include <cuda_runtime.h>
#include <cstdint>

#define BB 8
#define SS 1024
#define DD 1024
#define HH 16
#define HD 64

// Scratch (device globals). tf32-rounded fp32 bits, K-dims permuted within
// 8-groups: pos(k) = 2*(k&3) + (k>>2), so frag pairs (t, t+4) are adjacent.
__device__ float g_Q[BB*HH*SS*HD];          // [b][h][s][hd_perm]
__device__ float g_K[BB*HH*SS*HD];          // [b][h][s][hd_perm]
__device__ float g_Vt[BB*HH*HD*SS];         // [b][h][hd][s]   (transposed)
__device__ float g_C[(size_t)BB*SS*DD];     // [b][s][dd_perm]
__device__ float g_Wo[DD*DD];               // [n][dd_perm]

// ---------------- helpers ----------------
static __device__ __forceinline__ int posk(int c) { return 2 * (c & 3) + ((c >> 2) & 1); }
static __device__ __forceinline__ uint32_t cvt_tf32(float f) {
    uint32_t u; asm("cvt.rna.tf32.f32 %0, %1;" : "=r"(u) : "f"(f)); return u;
}
static __device__ __forceinline__ float cvtf(float f) { return __uint_as_float(cvt_tf32(f)); }
static __device__ __forceinline__ float ex2f(float x) {
    float y; asm("ex2.approx.f32 %0, %1;" : "=f"(y) : "f"(x)); return y;
}
static __device__ __forceinline__ void mma8(float* d, const uint32_t* a, const uint32_t* b) {
    asm volatile("mma.sync.aligned.m16n8k8.row.col.f32.tf32.tf32.f32 "
        "{%0,%1,%2,%3}, {%4,%5,%6,%7}, {%8,%9}, {%0,%1,%2,%3};"
        : "+f"(d[0]), "+f"(d[1]), "+f"(d[2]), "+f"(d[3])
        : "r"(a[0]), "r"(a[1]), "r"(a[2]), "r"(a[3]), "r"(b[0]), "r"(b[1]));
}
// A frag from k-permuted smem: one float2 per row. a = {f0.x, f1.x, f0.y, f1.y}.
static __device__ __forceinline__ void lda2(uint32_t* a, const float* s, int P,
                                            int r0, int k0, int g, int t) {
    float2 f0 = *(const float2*)&s[(r0 + g) * P + k0 + 2 * t];
    float2 f1 = *(const float2*)&s[(r0 + g + 8) * P + k0 + 2 * t];
    a[0] = __float_as_uint(f0.x); a[1] = __float_as_uint(f1.x);
    a[2] = __float_as_uint(f0.y); a[3] = __float_as_uint(f1.y);
}
// B frag ([n][k_perm] storage): one float2.
static __device__ __forceinline__ void ldb2(uint32_t* b, const float* s, int P,
                                            int n0, int k0, int g, int t) {
    float2 f = *(const float2*)&s[(n0 + g) * P + k0 + 2 * t];
    b[0] = __float_as_uint(f.x); b[1] = __float_as_uint(f.y);
}
static __device__ __forceinline__ uint32_t smem_u32(const void* p) {
    uint32_t a;
    asm("{ .reg .u64 t; cvta.to.shared.u64 t, %1; cvt.u32.u64 %0, t; }" : "=r"(a) : "l"(p));
    return a;
}
static __device__ __forceinline__ void cpa16(uint32_t dst, const void* src) {
    asm volatile("cp.async.ca.shared.global [%0], [%1], 16;" :: "r"(dst), "l"(src));
}
#define CP_COMMIT() asm volatile("cp.async.commit_group;" ::: "memory")
#define CP_WAIT(n)  asm volatile("cp.async.wait_group %0;" :: "n"(n) : "memory")

// ============================================================================
// Kernel 0: round + k-permute Wo.
// ============================================================================
__global__ void round_wo(const float* __restrict__ Wo) {
    int i = (blockIdx.x * 256 + threadIdx.x) * 4;
    float4 v = *(const float4*)&Wo[i];
    int r = i >> 10, c = i & 1023;
    float vv[4] = { v.x, v.y, v.z, v.w };
    #pragma unroll
    for (int j = 0; j < 4; ++j) {
        int cc = c + j;
        g_Wo[r * 1024 + (cc & ~7) + posk(cc & 7)] = cvtf(vv[j]);
    }
}

// ============================================================================
// Kernel 1: fused QKV projection. grid (8, 16, 8), 512 threads (16 warps).
// [128 rows x 64] x [64 x 192]. xs staged permuted+rounded; ws transposed
// permuted+rounded. Q/K written hd-permuted; V written transposed to g_Vt.
// ============================================================================
#define PPJ 72
#define PRJ_WS   (128 * PPJ)
#define PRJ_BIAS (PRJ_WS + 192 * PPJ)
#define PRJ_SMEM_F (PRJ_BIAS + 192)

__global__ __launch_bounds__(512) void proj_mma(
    const float* __restrict__ x,
    const float* __restrict__ Wq, const float* __restrict__ bq,
    const float* __restrict__ Wk, const float* __restrict__ bk,
    const float* __restrict__ Wv, const float* __restrict__ bv)
{
    extern __shared__ float sm[];
    float* xs = sm;
    float* ws = sm + PRJ_WS;
    float* sbias = sm + PRJ_BIAS;

    const int b = blockIdx.z, h = blockIdx.y, s0 = blockIdx.x * 128;
    const int tid = threadIdx.x, wid = tid >> 5, lane = tid & 31;
    const int g = lane >> 2, t = lane & 3;
    const int wr = wid & 3, wc = wid >> 2;
    const int r0 = wr * 32, c0 = wc * 48;

    // x: load raw, round, write k-permuted
    {
        float4 v[4]; int rr[4], cc[4];
        #pragma unroll
        for (int u = 0; u < 4; ++u) {
            int i = tid + u * 512;
            rr[u] = i >> 4; cc[u] = (i & 15) << 2;
            v[u] = *(const float4*)&x[((size_t)(b * SS + s0 + rr[u])) * DD + h * HD + cc[u]];
        }
        #pragma unroll
        for (int u = 0; u < 4; ++u) {
            float vv[4] = { v[u].x, v[u].y, v[u].z, v[u].w };
            #pragma unroll
            for (int j = 0; j < 4; ++j) {
                int c = cc[u] + j;
                xs[rr[u] * PPJ + (c & ~7) + posk(c & 7)] = cvtf(vv[j]);
            }
        }
    }
    // W: transpose + round + k-permute (k = input dim d)
    {
        const float* Wsrc[3] = { Wq + (size_t)h * HD * HD, Wk + (size_t)h * HD * HD,
                                 Wv + (size_t)h * HD * HD };
        for (int i = tid; i < 3 * 4096; i += 512) {
            int w = i >> 12, r = i & 4095, d = r >> 6, e = r & 63;
            ws[(w * 64 + e) * PPJ + (d & ~7) + posk(d & 7)] = cvtf(Wsrc[w][r]);
        }
        if (tid < 192) {
            int w = tid >> 6, e = tid & 63;
            const float* bsrc[3] = { bq, bk, bv };
            sbias[tid] = bsrc[w][h * HD + e];
        }
    }
    __syncthreads();

    float acc[2][6][4] = {};
    #pragma unroll
    for (int kk = 0; kk < 8; ++kk) {
        uint32_t a0[4], a1[4];
        lda2(a0, xs, PPJ, r0, kk * 8, g, t);
        lda2(a1, xs, PPJ, r0 + 16, kk * 8, g, t);
        #pragma unroll
        for (int n = 0; n < 6; ++n) {
            uint32_t bb[2];
            ldb2(bb, ws, PPJ, c0 + n * 8, kk * 8, g, t);
            mma8(acc[0][n], a0, bb);
            mma8(acc[1][n], a1, bb);
        }
    }

    const size_t bhS = (size_t)(b * HH + h) * SS;
    const size_t bhD = (size_t)(b * HH + h) * HD;
    #pragma unroll
    for (int m = 0; m < 2; ++m) {
        #pragma unroll
        for (int n = 0; n < 6; ++n) {
            int gcol = c0 + n * 8 + t * 2;
            int w = gcol >> 6, lcol = gcol & 63;
            float b0 = sbias[gcol], b1 = sbias[gcol + 1];
            int row = s0 + r0 + m * 16 + g;
            float o00 = cvtf(acc[m][n][0] + b0), o01 = cvtf(acc[m][n][1] + b1);
            float o10 = cvtf(acc[m][n][2] + b0), o11 = cvtf(acc[m][n][3] + b1);
            if (w < 2) {
                float* outp = w ? g_K : g_Q;
                int p0 = (lcol & ~7) + posk(lcol & 7);
                int p1 = ((lcol + 1) & ~7) + posk((lcol + 1) & 7);
                outp[(bhS + row) * HD + p0] = o00;
                outp[(bhS + row) * HD + p1] = o01;
                outp[(bhS + row + 8) * HD + p0] = o10;
                outp[(bhS + row + 8) * HD + p1] = o11;
            } else {   // V transposed, unpermuted
                g_Vt[(bhD + lcol) * SS + row] = o00;
                g_Vt[(bhD + lcol + 1) * SS + row] = o01;
                g_Vt[(bhD + lcol) * SS + row + 8] = o10;
                g_Vt[(bhD + lcol + 1) * SS + row + 8] = o11;
            }
        }
    }
}

// ============================================================================
// Kernel 2: flash attention. grid (8, 16, 8), 128 threads (4 warps),
// ~110KB smem -> 2 CTAs/SM. CTA = 128 queries, warp M=32, key halves of 64.
// Q/K tiles k-permuted (float2 frags); V tile transposed [hd][key] so PV
// B-frags are float2 under the p0/p2/p1/p3 A permutation (key = pos(k)).
// ============================================================================
#define PAK 72
#define PVT 136
#define AO_K 0
#define AO_Q (128 * PAK)
#define AO_V (2 * 128 * PAK)
#define AO_M (AO_V + 64 * PVT)
#define ATTN_F (AO_M + 1024)
#define EXPC 0.18033688f   // 0.125 * log2(e)

static __device__ __forceinline__ void s_half(float p[2][8][4], const float* Qs,
                                              const float* Ks, int r0, int n0,
                                              int g, int t) {
    #pragma unroll
    for (int m = 0; m < 2; ++m)
        #pragma unroll
        for (int n = 0; n < 8; ++n)
            #pragma unroll
            for (int j = 0; j < 4; ++j) p[m][n][j] = 0.f;
    #pragma unroll
    for (int kk = 0; kk < 8; ++kk) {
        uint32_t a0[4], a1[4];
        lda2(a0, Qs, PAK, r0, kk * 8, g, t);
        lda2(a1, Qs, PAK, r0 + 16, kk * 8, g, t);
        #pragma unroll
        for (int n = 0; n < 8; ++n) {
            uint32_t bb[2];
            ldb2(bb, Ks, PAK, n0 + n * 8, kk * 8, g, t);
            mma8(p[0][n], a0, bb);
            mma8(p[1][n], a1, bb);
        }
    }
}

static __device__ __forceinline__ void exp_half(float p[2][8][4], const float* mmk,
                                                float rs[2][2], int t) {
    #pragma unroll
    for (int m = 0; m < 2; ++m)
        #pragma unroll
        for (int n = 0; n < 8; ++n) {
            float2 mv = *(const float2*)&mmk[n * 8 + t * 2];
            p[m][n][0] = ex2f(p[m][n][0] * EXPC) * mv.x;
            p[m][n][1] = ex2f(p[m][n][1] * EXPC) * mv.y;
            p[m][n][2] = ex2f(p[m][n][2] * EXPC) * mv.x;
            p[m][n][3] = ex2f(p[m][n][3] * EXPC) * mv.y;
            rs[m][0] += p[m][n][0] + p[m][n][1];
            rs[m][1] += p[m][n][2] + p[m][n][3];
        }
}

// PV: A = P D-frag as {p0,p2,p1,p3} (logical k=t <-> key 2t = pos(t));
// B = Vt[hd][key]: float2 at keys (k0+2t, k0+2t+1) = (pos(t), pos(t+4)).
static __device__ __forceinline__ void pv_half(float o[2][8][4], const float p[2][8][4],
                                               const float* Vt, int k0, int g, int t) {
    #pragma unroll
    for (int kkp = 0; kkp < 8; ++kkp) {
        uint32_t A0[4] = { __float_as_uint(p[0][kkp][0]), __float_as_uint(p[0][kkp][2]),
                           __float_as_uint(p[0][kkp][1]), __float_as_uint(p[0][kkp][3]) };
        uint32_t A1[4] = { __float_as_uint(p[1][kkp][0]), __float_as_uint(p[1][kkp][2]),
                           __float_as_uint(p[1][kkp][1]), __float_as_uint(p[1][kkp][3]) };
        #pragma unroll
        for (int n = 0; n < 8; ++n) {
            uint32_t bb[2];
            ldb2(bb, Vt, PVT, n * 8, k0 + kkp * 8, g, t);
            mma8(o[0][n], A0, bb);
            mma8(o[1][n], A1, bb);
        }
    }
}

__global__ __launch_bounds__(128, 2) void attn_mma(const int* __restrict__ mask)
{
    extern __shared__ float sm[];
    float* Ks = sm + AO_K;
    float* Qs = sm + AO_Q;
    float* Vt = sm + AO_V;
    float* mm = sm + AO_M;
    const uint32_t sb = smem_u32(sm);

    const int b = blockIdx.z, h = blockIdx.y, q0 = blockIdx.x * 128;
    const int tid = threadIdx.x, wid = tid >> 5, lane = tid & 31;
    const int g = lane >> 2, t = lane & 3;
    const int r0 = wid * 32;

    const size_t bh = (size_t)(b * HH + h);
    const float* Qp = g_Q + bh * SS * HD;
    const float* Kp = g_K + bh * SS * HD;
    const float* Vp = g_Vt + bh * HD * SS;

    // prologue: K(0) | Vt(0)+Q async; mask direct
    for (int i = tid; i < 128 * 16; i += 128) {
        int r = i >> 4, c4 = (i & 15) << 2;
        cpa16(sb + (uint32_t)(AO_K + r * PAK + c4) * 4, &Kp[(size_t)r * HD + c4]);
    }
    CP_COMMIT();
    for (int i = tid; i < 128 * 16; i += 128) {
        int r = i >> 4, c4 = (i & 15) << 2;
        cpa16(sb + (uint32_t)(AO_Q + r * PAK + c4) * 4, &Qp[(size_t)(q0 + r) * HD + c4]);
    }
    for (int i = tid; i < 64 * 32; i += 128) {
        int r = i >> 5, c4 = (i & 31) << 2;
        cpa16(sb + (uint32_t)(AO_V + r * PVT + c4) * 4, &Vp[(size_t)r * SS + c4]);
    }
    CP_COMMIT();
    for (int i = tid; i < SS; i += 128)
        mm[i] = mask[(size_t)b * SS + i] ? 0.f : 1.f;
    CP_WAIT(0);
    __syncthreads();

    float o[2][8][4] = {};
    float rs[2][2] = {};
    float p[2][8][4];

    for (int kt = 0; kt < 8; ++kt) {
        CP_WAIT(1);           // K(kt) ready; no-op at kt=0
        __syncthreads();

        // half 0: keys [0,64)
        s_half(p, Qs, Ks, r0, 0, g, t);
        exp_half(p, mm + kt * 128, rs, t);
        CP_WAIT(0);           // Vt(kt) ready
        __syncthreads();
        pv_half(o, p, Vt, 0, g, t);

        // half 1: keys [64,128)
        s_half(p, Qs, Ks, r0, 64, g, t);
        exp_half(p, mm + kt * 128 + 64, rs, t);
        __syncthreads();      // all warps done reading Ks
        if (kt + 1 < 8) {
            for (int i = tid; i < 128 * 16; i += 128) {
                int r = i >> 4, c4 = (i & 15) << 2;
                cpa16(sb + (uint32_t)(AO_K + r * PAK + c4) * 4,
                      &Kp[(size_t)((kt + 1) * 128 + r) * HD + c4]);
            }
        }
        CP_COMMIT();          // group: K(kt+1) (empty at kt=7)
        pv_half(o, p, Vt, 64, g, t);
        __syncthreads();      // all warps done reading Vt
        if (kt + 1 < 8) {
            for (int i = tid; i < 64 * 32; i += 128) {
                int r = i >> 5, c4 = (i & 31) << 2;
                cpa16(sb + (uint32_t)(AO_V + r * PVT + c4) * 4,
                      &Vp[(size_t)r * SS + (kt + 1) * 128 + c4]);
            }
        }
        CP_COMMIT();          // group: Vt(kt+1) (empty at kt=7)
    }

    // row sums: quad-reduce
    #pragma unroll
    for (int m = 0; m < 2; ++m)
        #pragma unroll
        for (int j = 0; j < 2; ++j) {
            rs[m][j] += __shfl_xor_sync(0xffffffffu, rs[m][j], 1);
            rs[m][j] += __shfl_xor_sync(0xffffffffu, rs[m][j], 2);
        }

    // O store: dd-permuted scalar stores (g_C feeds outproj's permuted k)
    #pragma unroll
    for (int m = 0; m < 2; ++m) {
        const float inv0 = 1.0f / rs[m][0], inv1 = 1.0f / rs[m][1];
        const int row = q0 + r0 + m * 16 + g;
        #pragma unroll
        for (int n = 0; n < 8; ++n) {
            int c = n * 8 + t * 2;
            int p0 = (c & ~7) + posk(c & 7);
            int p1 = ((c + 1) & ~7) + posk((c + 1) & 7);
            size_t base0 = ((size_t)(b * SS + row)) * DD + h * HD;
            size_t base1 = ((size_t)(b * SS + row + 8)) * DD + h * HD;
            g_C[base0 + p0] = cvtf(o[m][n][0] * inv0);
            g_C[base0 + p1] = cvtf(o[m][n][1] * inv0);
            g_C[base1 + p0] = cvtf(o[m][n][2] * inv1);
            g_C[base1 + p1] = cvtf(o[m][n][3] * inv1);
        }
    }
}

// ============================================================================
// Kernel 3: out-proj Y = C @ Wo^T + bo. grid (8, 64), 256 threads.
// Block 128x128, warp 32x64, double-buffered k-chunks of 32, pitch 40
// (80KB smem -> 2 CTAs/SM). Both operands k-permuted -> float2 frags.
// ============================================================================
#define PO 40
#define OB_STRIDE (2 * 128 * PO)

__global__ __launch_bounds__(256, 2) void outproj_mma(
    const float* __restrict__ bo, float* __restrict__ y)
{
    extern __shared__ float sm[];
    const uint32_t sb = smem_u32(sm);

    const int n0 = blockIdx.x * 128;
    const int m0 = blockIdx.y * 128;
    const int tid = threadIdx.x, wid = tid >> 5, lane = tid & 31;
    const int g = lane >> 2, t = lane & 3;
    const int wr = wid & 3, wc = wid >> 2;
    const int r0 = wr * 32, c0 = wc * 64;

    auto issue = [&](int ch, int buf) {
        const uint32_t bofs = (uint32_t)(buf * OB_STRIDE);
        for (int i = tid; i < 128 * 8; i += 256) {
            int r = i >> 3, c4 = (i & 7) << 2;
            cpa16(sb + (bofs + (uint32_t)(r * PO + c4)) * 4,
                  &g_C[(size_t)(m0 + r) * DD + ch * 32 + c4]);
            cpa16(sb + (bofs + (uint32_t)(128 * PO + r * PO + c4)) * 4,
                  &g_Wo[(size_t)(n0 + r) * DD + ch * 32 + c4]);
        }
        CP_COMMIT();
    };
    issue(0, 0);
    issue(1, 1);

    float acc[2][8][4] = {};
    for (int ch = 0; ch < 32; ++ch) {
        CP_WAIT(1);
        __syncthreads();
        const float* Cs = sm + (ch & 1) * OB_STRIDE;
        const float* Ws = Cs + 128 * PO;
        #pragma unroll
        for (int kk = 0; kk < 4; ++kk) {
            uint32_t a0[4], a1[4];
            lda2(a0, Cs, PO, r0, kk * 8, g, t);
            lda2(a1, Cs, PO, r0 + 16, kk * 8, g, t);
            #pragma unroll
            for (int n = 0; n < 8; ++n) {
                uint32_t bb[2];
                ldb2(bb, Ws, PO, c0 + n * 8, kk * 8, g, t);
                mma8(acc[0][n], a0, bb);
                mma8(acc[1][n], a1, bb);
            }
        }
        __syncthreads();
        if (ch + 2 < 32) issue(ch + 2, ch & 1);
        else CP_COMMIT();
    }

    #pragma unroll
    for (int m = 0; m < 2; ++m) {
        #pragma unroll
        for (int n = 0; n < 8; ++n) {
            int col = c0 + n * 8 + t * 2;
            float b0 = bo[n0 + col], b1 = bo[n0 + col + 1];
            int row = m0 + r0 + m * 16 + g;
            size_t base0 = (size_t)row * DD + n0 + col;
            size_t base1 = (size_t)(row + 8) * DD + n0 + col;
            *(float2*)&y[base0] = make_float2(acc[m][n][0] + b0, acc[m][n][1] + b1);
            *(float2*)&y[base1] = make_float2(acc[m][n][2] + b0, acc[m][n][3] + b1);
        }
    }
}

// ============================================================================
extern "C" void kernel_launch(void* const* d_in, const int* in_sizes, int n_in,
                              void* d_out, int out_size)
{
    const float* x  = (const float*)d_in[0];
    const int* mk   = (const int*)d_in[1];
    const float* Wq = (const float*)d_in[2];
    const float* bq = (const float*)d_in[3];
    const float* Wk = (const float*)d_in[4];
    const float* bk = (const float*)d_in[5];
    const float* Wv = (const float*)d_in[6];
    const float* bv = (const float*)d_in[7];
    const float* Wo = (const float*)d_in[8];
    const float* bo = (const float*)d_in[9];
    float* y = (float*)d_out;

    const int smem_proj = PRJ_SMEM_F * 4;     // ~93 KB
    const int smem_attn = ATTN_F * 4;         // ~113 KB -> 2 CTAs/SM
    const int smem_out  = 2 * OB_STRIDE * 4;  // ~80 KB -> 2 CTAs/SM
    cudaFuncSetAttribute(proj_mma, cudaFuncAttributeMaxDynamicSharedMemorySize, smem_proj);
    cudaFuncSetAttribute(attn_mma, cudaFuncAttributeMaxDynamicSharedMemorySize, smem_attn);
    cudaFuncSetAttribute(outproj_mma, cudaFuncAttributeMaxDynamicSharedMemorySize, smem_out);

    round_wo<<<DD * DD / 1024, 256>>>(Wo);
    proj_mma<<<dim3(SS / 128, HH, BB), 512, smem_proj>>>(x, Wq, bq, Wk, bk, Wv, bv);
    attn_mma<<<dim3(SS / 128, HH, BB), 128, smem_attn>>>(mk);
    outproj_mma<<<dim3(DD / 128, BB * SS / 128), 256, smem_out>>>(bo, y);
}

// round 10
// speedup vs baseline: 1.1115x; 1.1115x over previous
#include <cuda_runtime.h>
#include <cstdint>

#define BB 8
#define SS 1024
#define DD 1024
#define HH 16
#define HD 64

// Scratch (device globals). All contents tf32-rounded fp32 (rounded once, rna).
__device__ float g_Q[BB*HH*SS*HD];
__device__ float g_K[BB*HH*SS*HD];
__device__ float g_V[BB*HH*SS*HD];
__device__ float g_C[(size_t)BB*SS*DD];
__device__ float g_Wo[DD*DD];

// ---------------- helpers ----------------
static __device__ __forceinline__ uint32_t cvt_tf32(float f) {
    uint32_t u; asm("cvt.rna.tf32.f32 %0, %1;" : "=r"(u) : "f"(f)); return u;
}
static __device__ __forceinline__ float cvtf(float f) { return __uint_as_float(cvt_tf32(f)); }
static __device__ __forceinline__ float ex2f(float x) {
    float y; asm("ex2.approx.f32 %0, %1;" : "=f"(y) : "f"(x)); return y;
}
static __device__ __forceinline__ void mma8(float* d, const uint32_t* a, const uint32_t* b) {
    asm volatile("mma.sync.aligned.m16n8k8.row.col.f32.tf32.tf32.f32 "
        "{%0,%1,%2,%3}, {%4,%5,%6,%7}, {%8,%9}, {%0,%1,%2,%3};"
        : "+f"(d[0]), "+f"(d[1]), "+f"(d[2]), "+f"(d[3])
        : "r"(a[0]), "r"(a[1]), "r"(a[2]), "r"(a[3]), "r"(b[0]), "r"(b[1]));
}
static __device__ __forceinline__ void lda(uint32_t* a, const float* s, int P,
                                           int r0, int k0, int g, int t) {
    a[0] = __float_as_uint(s[(r0 + g) * P + k0 + t]);
    a[1] = __float_as_uint(s[(r0 + g + 8) * P + k0 + t]);
    a[2] = __float_as_uint(s[(r0 + g) * P + k0 + t + 4]);
    a[3] = __float_as_uint(s[(r0 + g + 8) * P + k0 + t + 4]);
}
static __device__ __forceinline__ void ldb_nk(uint32_t* b, const float* s, int P,
                                              int n0, int k0, int g, int t) {
    b[0] = __float_as_uint(s[(n0 + g) * P + k0 + t]);
    b[1] = __float_as_uint(s[(n0 + g) * P + k0 + t + 4]);
}
static __device__ __forceinline__ uint32_t smem_u32(const void* p) {
    uint32_t a;
    asm("{ .reg .u64 t; cvta.to.shared.u64 t, %1; cvt.u32.u64 %0, t; }" : "=r"(a) : "l"(p));
    return a;
}
static __device__ __forceinline__ void cpa16(uint32_t dst, const void* src) {
    asm volatile("cp.async.ca.shared.global [%0], [%1], 16;" :: "r"(dst), "l"(src));
}
#define CP_COMMIT() asm volatile("cp.async.commit_group;" ::: "memory")
#define CP_WAIT(n)  asm volatile("cp.async.wait_group %0;" :: "n"(n) : "memory")

// ============================================================================
// Kernel 1: fused QKV projection + Wo rounding tail. grid (8, 16, 8),
// 512 threads (16 warps). [128 rows x 64] x [64 x 192].
// Each thread also rounds 2 Wo elements (removes the round_wo launch;
// stream order guarantees completion before outproj).
// ============================================================================
#define PP 68
#define PRJ_WS   (128 * PP)
#define PRJ_BIAS (128 * PP + 192 * PP)
#define PRJ_SMEM_F (PRJ_BIAS + 192)

__global__ __launch_bounds__(512) void proj_mma(
    const float* __restrict__ x,
    const float* __restrict__ Wq, const float* __restrict__ bq,
    const float* __restrict__ Wk, const float* __restrict__ bk,
    const float* __restrict__ Wv, const float* __restrict__ bv,
    const float* __restrict__ Wo)
{
    extern __shared__ float sm[];
    float* xs = sm;
    float* ws = sm + PRJ_WS;
    float* sbias = sm + PRJ_BIAS;
    const uint32_t sb = smem_u32(sm);

    const int b = blockIdx.z, h = blockIdx.y, s0 = blockIdx.x * 128;
    const int tid = threadIdx.x, wid = tid >> 5, lane = tid & 31;
    const int g = lane >> 2, t = lane & 3;
    const int wr = wid & 3, wc = wid >> 2;
    const int r0 = wr * 32, c0 = wc * 48;

    for (int i = tid; i < 128 * 16; i += 512) {
        int r = i >> 4, c4 = (i & 15) << 2;
        cpa16(sb + (uint32_t)(r * PP + c4) * 4,
              &x[((size_t)(b * SS + s0 + r)) * DD + h * HD + c4]);
    }
    CP_COMMIT();

    {
        const float* Wsrc[3] = { Wq + (size_t)h * HD * HD, Wk + (size_t)h * HD * HD,
                                 Wv + (size_t)h * HD * HD };
        for (int i = tid; i < 3 * 4096; i += 512) {
            int w = i >> 12, r = i & 4095, d = r >> 6, e = r & 63;
            ws[(w * 64 + e) * PP + d] = cvtf(Wsrc[w][r]);
        }
        if (tid < 192) {
            int w = tid >> 6, e = tid & 63;
            const float* bsrc[3] = { bq, bk, bv };
            sbias[tid] = bsrc[w][h * HD + e];
        }
    }
    // Wo rounding slice: flat block id * 1024 + tid*2, two floats per thread
    {
        int blk = (blockIdx.z * HH + blockIdx.y) * 8 + blockIdx.x;   // 0..1023
        size_t idx = (size_t)blk * 1024 + tid * 2;
        float2 v = *(const float2*)&Wo[idx];
        *(float2*)&g_Wo[idx] = make_float2(cvtf(v.x), cvtf(v.y));
    }
    CP_WAIT(0);
    __syncthreads();
    // in-place tf32 rounding of staged x
    for (int i = tid; i < 128 * 16; i += 512) {
        int r = i >> 4, c4 = (i & 15) << 2;
        float4 v = *(float4*)&xs[r * PP + c4];
        *(float4*)&xs[r * PP + c4] = make_float4(cvtf(v.x), cvtf(v.y), cvtf(v.z), cvtf(v.w));
    }
    __syncthreads();

    float acc[2][6][4] = {};
    #pragma unroll
    for (int kk = 0; kk < 8; ++kk) {
        uint32_t a0[4], a1[4];
        lda(a0, xs, PP, r0, kk * 8, g, t);
        lda(a1, xs, PP, r0 + 16, kk * 8, g, t);
        #pragma unroll
        for (int n = 0; n < 6; ++n) {
            uint32_t bb[2];
            ldb_nk(bb, ws, PP, c0 + n * 8, kk * 8, g, t);
            mma8(acc[0][n], a0, bb);
            mma8(acc[1][n], a1, bb);
        }
    }

    float* gdst[3] = { g_Q, g_K, g_V };
    #pragma unroll
    for (int m = 0; m < 2; ++m) {
        #pragma unroll
        for (int n = 0; n < 6; ++n) {
            int gcol = c0 + n * 8 + t * 2;
            int w = gcol >> 6, lcol = gcol & 63;
            float b0 = sbias[gcol], b1 = sbias[gcol + 1];
            int row = s0 + r0 + m * 16 + g;
            float* outp = gdst[w];
            size_t base0 = ((size_t)((b * HH + h) * SS + row)) * HD + lcol;
            size_t base1 = ((size_t)((b * HH + h) * SS + row + 8)) * HD + lcol;
            *(float2*)&outp[base0] = make_float2(cvtf(acc[m][n][0] + b0), cvtf(acc[m][n][1] + b1));
            *(float2*)&outp[base1] = make_float2(cvtf(acc[m][n][2] + b0), cvtf(acc[m][n][3] + b1));
        }
    }
}

// ============================================================================
// Kernel 2: flash attention (R8-identical). grid (8, 16, 8), 128 threads,
// 108.5KB smem -> 2 CTAs/SM. CTA = 128 queries; warp M=32; key halves of 64.
// ============================================================================
#define PA  68
#define AO_K 0
#define AO_V (128 * PA)
#define AO_Q (2 * 128 * PA)
#define AO_M (3 * 128 * PA)
#define ATTN_F (AO_M + 1024)
#define EXPC 0.18033688f   // 0.125 * log2(e)

static __device__ __forceinline__ void s_half(float p[2][8][4], const float* Qs,
                                              const float* Ks, int r0, int n0,
                                              int g, int t) {
    #pragma unroll
    for (int m = 0; m < 2; ++m)
        #pragma unroll
        for (int n = 0; n < 8; ++n)
            #pragma unroll
            for (int j = 0; j < 4; ++j) p[m][n][j] = 0.f;
    #pragma unroll
    for (int kk = 0; kk < 8; ++kk) {
        uint32_t a0[4], a1[4];
        lda(a0, Qs, PA, r0, kk * 8, g, t);
        lda(a1, Qs, PA, r0 + 16, kk * 8, g, t);
        #pragma unroll
        for (int n = 0; n < 8; ++n) {
            uint32_t bb[2];
            ldb_nk(bb, Ks, PA, n0 + n * 8, kk * 8, g, t);
            mma8(p[0][n], a0, bb);
            mma8(p[1][n], a1, bb);
        }
    }
}

static __device__ __forceinline__ void exp_half(float p[2][8][4], const float* mmk,
                                                float rs[2][2], int t) {
    #pragma unroll
    for (int m = 0; m < 2; ++m)
        #pragma unroll
        for (int n = 0; n < 8; ++n) {
            float2 mv = *(const float2*)&mmk[n * 8 + t * 2];
            p[m][n][0] = ex2f(p[m][n][0] * EXPC) * mv.x;
            p[m][n][1] = ex2f(p[m][n][1] * EXPC) * mv.y;
            p[m][n][2] = ex2f(p[m][n][2] * EXPC) * mv.x;
            p[m][n][3] = ex2f(p[m][n][3] * EXPC) * mv.y;
            rs[m][0] += p[m][n][0] + p[m][n][1];
            rs[m][1] += p[m][n][2] + p[m][n][3];
        }
}

static __device__ __forceinline__ void pv_half(float o[2][8][4], const float p[2][8][4],
                                               const float* Vs, int n0, int g, int t) {
    #pragma unroll
    for (int kkp = 0; kkp < 8; ++kkp) {
        uint32_t A0[4] = { __float_as_uint(p[0][kkp][0]), __float_as_uint(p[0][kkp][2]),
                           __float_as_uint(p[0][kkp][1]), __float_as_uint(p[0][kkp][3]) };
        uint32_t A1[4] = { __float_as_uint(p[1][kkp][0]), __float_as_uint(p[1][kkp][2]),
                           __float_as_uint(p[1][kkp][1]), __float_as_uint(p[1][kkp][3]) };
        const float* vrow0 = Vs + (n0 + kkp * 8 + 2 * t) * PA;
        const float* vrow1 = vrow0 + PA;
        #pragma unroll
        for (int n = 0; n < 8; ++n) {
            uint32_t bb[2];
            bb[0] = __float_as_uint(vrow0[n * 8 + g]);
            bb[1] = __float_as_uint(vrow1[n * 8 + g]);
            mma8(o[0][n], A0, bb);
            mma8(o[1][n], A1, bb);
        }
    }
}

__global__ __launch_bounds__(128, 2) void attn_mma(const int* __restrict__ mask)
{
    extern __shared__ float sm[];
    float* Ks = sm + AO_K;
    float* Vs = sm + AO_V;
    float* Qs = sm + AO_Q;
    float* mm = sm + AO_M;
    const uint32_t sb = smem_u32(sm);

    const int b = blockIdx.z, h = blockIdx.y, q0 = blockIdx.x * 128;
    const int tid = threadIdx.x, wid = tid >> 5, lane = tid & 31;
    const int g = lane >> 2, t = lane & 3;
    const int r0 = wid * 32;

    const size_t bh = (size_t)(b * HH + h) * SS * HD;
    const float* Qp = g_Q + bh;
    const float* Kp = g_K + bh;
    const float* Vp = g_V + bh;

    for (int i = tid; i < 128 * 16; i += 128) {
        int r = i >> 4, c4 = (i & 15) << 2;
        cpa16(sb + (uint32_t)(AO_K + r * PA + c4) * 4, &Kp[(size_t)r * HD + c4]);
    }
    CP_COMMIT();
    for (int i = tid; i < 128 * 16; i += 128) {
        int r = i >> 4, c4 = (i & 15) << 2;
        cpa16(sb + (uint32_t)(AO_V + r * PA + c4) * 4, &Vp[(size_t)r * HD + c4]);
        cpa16(sb + (uint32_t)(AO_Q + r * PA + c4) * 4, &Qp[(size_t)(q0 + r) * HD + c4]);
    }
    CP_COMMIT();
    for (int i = tid; i < SS; i += 128)
        mm[i] = mask[(size_t)b * SS + i] ? 0.f : 1.f;
    CP_WAIT(0);
    __syncthreads();

    float o[2][8][4] = {};
    float rs[2][2] = {};
    float p[2][8][4];

    for (int kt = 0; kt < 8; ++kt) {
        CP_WAIT(1);
        __syncthreads();

        s_half(p, Qs, Ks, r0, 0, g, t);
        exp_half(p, mm + kt * 128, rs, t);
        CP_WAIT(0);
        __syncthreads();
        pv_half(o, p, Vs, 0, g, t);

        s_half(p, Qs, Ks, r0, 64, g, t);
        exp_half(p, mm + kt * 128 + 64, rs, t);
        __syncthreads();
        if (kt + 1 < 8) {
            for (int i = tid; i < 128 * 16; i += 128) {
                int r = i >> 4, c4 = (i & 15) << 2;
                cpa16(sb + (uint32_t)(AO_K + r * PA + c4) * 4,
                      &Kp[(size_t)((kt + 1) * 128 + r) * HD + c4]);
            }
        }
        CP_COMMIT();
        pv_half(o, p, Vs, 64, g, t);
        __syncthreads();
        if (kt + 1 < 8) {
            for (int i = tid; i < 128 * 16; i += 128) {
                int r = i >> 4, c4 = (i & 15) << 2;
                cpa16(sb + (uint32_t)(AO_V + r * PA + c4) * 4,
                      &Vp[(size_t)((kt + 1) * 128 + r) * HD + c4]);
            }
        }
        CP_COMMIT();
    }

    #pragma unroll
    for (int m = 0; m < 2; ++m)
        #pragma unroll
        for (int j = 0; j < 2; ++j) {
            rs[m][j] += __shfl_xor_sync(0xffffffffu, rs[m][j], 1);
            rs[m][j] += __shfl_xor_sync(0xffffffffu, rs[m][j], 2);
        }

    #pragma unroll
    for (int m = 0; m < 2; ++m) {
        const float inv0 = 1.0f / rs[m][0], inv1 = 1.0f / rs[m][1];
        const int row = q0 + r0 + m * 16 + g;
        #pragma unroll
        for (int n = 0; n < 8; ++n) {
            int col = n * 8 + t * 2;
            size_t base0 = ((size_t)(b * SS + row)) * DD + h * HD + col;
            size_t base1 = ((size_t)(b * SS + row + 8)) * DD + h * HD + col;
            *(float2*)&g_C[base0] = make_float2(cvtf(o[m][n][0] * inv0), cvtf(o[m][n][1] * inv0));
            *(float2*)&g_C[base1] = make_float2(cvtf(o[m][n][2] * inv1), cvtf(o[m][n][3] * inv1));
        }
    }
}

// ============================================================================
// Kernel 3: out-proj Y = C @ Wo^T + bo. grid (8, 64), 256 threads.
// Block 128x128, warp 32x64, cp.async THREE-stage pipeline of k-chunks of 32
// (110.6KB smem -> 2 CTAs/SM; two chunks in flight during each compute).
// ============================================================================
#define PO 36
#define OB_STRIDE (2 * 128 * PO)

__global__ __launch_bounds__(256, 2) void outproj_mma(
    const float* __restrict__ bo, float* __restrict__ y)
{
    extern __shared__ float sm[];
    const uint32_t sb = smem_u32(sm);

    const int n0 = blockIdx.x * 128;
    const int m0 = blockIdx.y * 128;
    const int tid = threadIdx.x, wid = tid >> 5, lane = tid & 31;
    const int g = lane >> 2, t = lane & 3;
    const int wr = wid & 3, wc = wid >> 2;
    const int r0 = wr * 32, c0 = wc * 64;

    auto issue = [&](int ch, int buf) {
        const uint32_t bofs = (uint32_t)(buf * OB_STRIDE);
        for (int i = tid; i < 128 * 8; i += 256) {
            int r = i >> 3, c4 = (i & 7) << 2;
            cpa16(sb + (bofs + (uint32_t)(r * PO + c4)) * 4,
                  &g_C[(size_t)(m0 + r) * DD + ch * 32 + c4]);
            cpa16(sb + (bofs + (uint32_t)(128 * PO + r * PO + c4)) * 4,
                  &g_Wo[(size_t)(n0 + r) * DD + ch * 32 + c4]);
        }
        CP_COMMIT();
    };
    issue(0, 0);
    issue(1, 1);
    issue(2, 2);

    float acc[2][8][4] = {};
    int buf = 0;
    for (int ch = 0; ch < 32; ++ch) {
        CP_WAIT(2);           // chunk ch resident; ch+1, ch+2 still in flight
        __syncthreads();
        const float* Cs = sm + buf * OB_STRIDE;
        const float* Ws = Cs + 128 * PO;
        #pragma unroll
        for (int kk = 0; kk < 4; ++kk) {
            uint32_t a0[4], a1[4];
            lda(a0, Cs, PO, r0, kk * 8, g, t);
            lda(a1, Cs, PO, r0 + 16, kk * 8, g, t);
            #pragma unroll
            for (int n = 0; n < 8; ++n) {
                uint32_t bb[2];
                ldb_nk(bb, Ws, PO, c0 + n * 8, kk * 8, g, t);
                mma8(acc[0][n], a0, bb);
                mma8(acc[1][n], a1, bb);
            }
        }
        __syncthreads();
        if (ch + 3 < 32) issue(ch + 3, buf);
        else CP_COMMIT();     // keep group accounting uniform
        buf = (buf == 2) ? 0 : buf + 1;
    }

    #pragma unroll
    for (int m = 0; m < 2; ++m) {
        #pragma unroll
        for (int n = 0; n < 8; ++n) {
            int col = c0 + n * 8 + t * 2;
            float b0 = bo[n0 + col], b1 = bo[n0 + col + 1];
            int row = m0 + r0 + m * 16 + g;
            size_t base0 = (size_t)row * DD + n0 + col;
            size_t base1 = (size_t)(row + 8) * DD + n0 + col;
            *(float2*)&y[base0] = make_float2(acc[m][n][0] + b0, acc[m][n][1] + b1);
            *(float2*)&y[base1] = make_float2(acc[m][n][2] + b0, acc[m][n][3] + b1);
        }
    }
}

// ============================================================================
extern "C" void kernel_launch(void* const* d_in, const int* in_sizes, int n_in,
                              void* d_out, int out_size)
{
    const float* x  = (const float*)d_in[0];
    const int* mk   = (const int*)d_in[1];
    const float* Wq = (const float*)d_in[2];
    const float* bq = (const float*)d_in[3];
    const float* Wk = (const float*)d_in[4];
    const float* bk = (const float*)d_in[5];
    const float* Wv = (const float*)d_in[6];
    const float* bv = (const float*)d_in[7];
    const float* Wo = (const float*)d_in[8];
    const float* bo = (const float*)d_in[9];
    float* y = (float*)d_out;

    const int smem_proj = PRJ_SMEM_F * 4;     // ~88 KB
    const int smem_attn = ATTN_F * 4;         // ~108.5 KB -> 2 CTAs/SM
    const int smem_out  = 3 * OB_STRIDE * 4;  // ~110.6 KB -> 2 CTAs/SM
    cudaFuncSetAttribute(proj_mma, cudaFuncAttributeMaxDynamicSharedMemorySize, smem_proj);
    cudaFuncSetAttribute(attn_mma, cudaFuncAttributeMaxDynamicSharedMemorySize, smem_attn);
    cudaFuncSetAttribute(outproj_mma, cudaFuncAttributeMaxDynamicSharedMemorySize, smem_out);

    proj_mma<<<dim3(SS / 128, HH, BB), 512, smem_proj>>>(x, Wq, bq, Wk, bk, Wv, bv, Wo);
    attn_mma<<<dim3(SS / 128, HH, BB), 128, smem_attn>>>(mk);
    outproj_mma<<<dim3(DD / 128, BB * SS / 128), 256, smem_out>>>(bo, y);
}

// round 11
// speedup vs baseline: 1.4558x; 1.3097x over previous
#include <cuda_runtime.h>
#include <cstdint>

#define BB 8
#define SS 1024
#define DD 1024
#define HH 16
#define HD 64

// Scratch (device globals). All contents tf32-rounded fp32 (rounded once, rna).
__device__ float g_Q[BB*HH*SS*HD];
__device__ float g_K[BB*HH*SS*HD];
__device__ float g_V[BB*HH*SS*HD];
__device__ float g_C[(size_t)BB*SS*DD];
__device__ float g_Wo[DD*DD];
__device__ int   g_idx[BB*SS];   // per-batch compacted unmasked key indices
__device__ int   g_nb[BB];       // per-batch unmasked count

// ---------------- helpers ----------------
static __device__ __forceinline__ uint32_t cvt_tf32(float f) {
    uint32_t u; asm("cvt.rna.tf32.f32 %0, %1;" : "=r"(u) : "f"(f)); return u;
}
static __device__ __forceinline__ float cvtf(float f) { return __uint_as_float(cvt_tf32(f)); }
static __device__ __forceinline__ float ex2f(float x) {
    float y; asm("ex2.approx.f32 %0, %1;" : "=f"(y) : "f"(x)); return y;
}
static __device__ __forceinline__ void mma8(float* d, const uint32_t* a, const uint32_t* b) {
    asm volatile("mma.sync.aligned.m16n8k8.row.col.f32.tf32.tf32.f32 "
        "{%0,%1,%2,%3}, {%4,%5,%6,%7}, {%8,%9}, {%0,%1,%2,%3};"
        : "+f"(d[0]), "+f"(d[1]), "+f"(d[2]), "+f"(d[3])
        : "r"(a[0]), "r"(a[1]), "r"(a[2]), "r"(a[3]), "r"(b[0]), "r"(b[1]));
}
static __device__ __forceinline__ void lda(uint32_t* a, const float* s, int P,
                                           int r0, int k0, int g, int t) {
    a[0] = __float_as_uint(s[(r0 + g) * P + k0 + t]);
    a[1] = __float_as_uint(s[(r0 + g + 8) * P + k0 + t]);
    a[2] = __float_as_uint(s[(r0 + g) * P + k0 + t + 4]);
    a[3] = __float_as_uint(s[(r0 + g + 8) * P + k0 + t + 4]);
}
static __device__ __forceinline__ void ldb_nk(uint32_t* b, const float* s, int P,
                                              int n0, int k0, int g, int t) {
    b[0] = __float_as_uint(s[(n0 + g) * P + k0 + t]);
    b[1] = __float_as_uint(s[(n0 + g) * P + k0 + t + 4]);
}
static __device__ __forceinline__ uint32_t smem_u32(const void* p) {
    uint32_t a;
    asm("{ .reg .u64 t; cvta.to.shared.u64 t, %1; cvt.u32.u64 %0, t; }" : "=r"(a) : "l"(p));
    return a;
}
static __device__ __forceinline__ void cpa16(uint32_t dst, const void* src) {
    asm volatile("cp.async.ca.shared.global [%0], [%1], 16;" :: "r"(dst), "l"(src));
}
#define CP_COMMIT() asm volatile("cp.async.commit_group;" ::: "memory")
#define CP_WAIT(n)  asm volatile("cp.async.wait_group %0;" :: "n"(n) : "memory")

// ============================================================================
// Kernel 0a: tf32-round Wo (once).
// ============================================================================
__global__ void round_wo(const float* __restrict__ Wo) {
    int i = (blockIdx.x * 256 + threadIdx.x) * 4;
    float4 v = *(const float4*)&Wo[i];
    *(float4*)&g_Wo[i] = make_float4(cvtf(v.x), cvtf(v.y), cvtf(v.z), cvtf(v.w));
}

// ============================================================================
// Kernel 0b: per-batch key compaction (sorted unmasked indices + count).
// grid = BB blocks x 1024 threads. Deterministic ballot+scan.
// ============================================================================
__global__ void build_idx(const int* __restrict__ mask) {
    __shared__ int wsum[33];
    const int b = blockIdx.x, tid = threadIdx.x;
    const int lane = tid & 31, w = tid >> 5;
    const int flag = mask[b * SS + tid] ? 0 : 1;   // 1 = unmasked (keep)
    unsigned bal = __ballot_sync(0xffffffffu, flag);
    int pre = __popc(bal & ((1u << lane) - 1u));
    if (lane == 0) wsum[w] = __popc(bal);
    __syncthreads();
    if (tid == 0) {
        int s = 0;
        for (int i = 0; i < 32; ++i) { int tt = wsum[i]; wsum[i] = s; s += tt; }
        wsum[32] = s;
        g_nb[b] = s;
    }
    __syncthreads();
    const int nb = wsum[32];
    if (tid >= nb) g_idx[b * SS + tid] = 0;          // pad slots -> row 0 (zeroed later)
    if (flag) g_idx[b * SS + wsum[w] + pre] = tid;   // distinct slots (< nb)
}

// ============================================================================
// Kernel 1: fused QKV projection (R8-identical). grid (8, 16, 8), 512 threads.
// ============================================================================
#define PP 68
#define PRJ_WS   (128 * PP)
#define PRJ_BIAS (128 * PP + 192 * PP)
#define PRJ_SMEM_F (PRJ_BIAS + 192)

__global__ __launch_bounds__(512) void proj_mma(
    const float* __restrict__ x,
    const float* __restrict__ Wq, const float* __restrict__ bq,
    const float* __restrict__ Wk, const float* __restrict__ bk,
    const float* __restrict__ Wv, const float* __restrict__ bv)
{
    extern __shared__ float sm[];
    float* xs = sm;
    float* ws = sm + PRJ_WS;
    float* sbias = sm + PRJ_BIAS;
    const uint32_t sb = smem_u32(sm);

    const int b = blockIdx.z, h = blockIdx.y, s0 = blockIdx.x * 128;
    const int tid = threadIdx.x, wid = tid >> 5, lane = tid & 31;
    const int g = lane >> 2, t = lane & 3;
    const int wr = wid & 3, wc = wid >> 2;
    const int r0 = wr * 32, c0 = wc * 48;

    for (int i = tid; i < 128 * 16; i += 512) {
        int r = i >> 4, c4 = (i & 15) << 2;
        cpa16(sb + (uint32_t)(r * PP + c4) * 4,
              &x[((size_t)(b * SS + s0 + r)) * DD + h * HD + c4]);
    }
    CP_COMMIT();

    {
        const float* Wsrc[3] = { Wq + (size_t)h * HD * HD, Wk + (size_t)h * HD * HD,
                                 Wv + (size_t)h * HD * HD };
        for (int i = tid; i < 3 * 4096; i += 512) {
            int w = i >> 12, r = i & 4095, d = r >> 6, e = r & 63;
            ws[(w * 64 + e) * PP + d] = cvtf(Wsrc[w][r]);
        }
        if (tid < 192) {
            int w = tid >> 6, e = tid & 63;
            const float* bsrc[3] = { bq, bk, bv };
            sbias[tid] = bsrc[w][h * HD + e];
        }
    }
    CP_WAIT(0);
    __syncthreads();
    for (int i = tid; i < 128 * 16; i += 512) {
        int r = i >> 4, c4 = (i & 15) << 2;
        float4 v = *(float4*)&xs[r * PP + c4];
        *(float4*)&xs[r * PP + c4] = make_float4(cvtf(v.x), cvtf(v.y), cvtf(v.z), cvtf(v.w));
    }
    __syncthreads();

    float acc[2][6][4] = {};
    #pragma unroll
    for (int kk = 0; kk < 8; ++kk) {
        uint32_t a0[4], a1[4];
        lda(a0, xs, PP, r0, kk * 8, g, t);
        lda(a1, xs, PP, r0 + 16, kk * 8, g, t);
        #pragma unroll
        for (int n = 0; n < 6; ++n) {
            uint32_t bb[2];
            ldb_nk(bb, ws, PP, c0 + n * 8, kk * 8, g, t);
            mma8(acc[0][n], a0, bb);
            mma8(acc[1][n], a1, bb);
        }
    }

    float* gdst[3] = { g_Q, g_K, g_V };
    #pragma unroll
    for (int m = 0; m < 2; ++m) {
        #pragma unroll
        for (int n = 0; n < 6; ++n) {
            int gcol = c0 + n * 8 + t * 2;
            int w = gcol >> 6, lcol = gcol & 63;
            float b0 = sbias[gcol], b1 = sbias[gcol + 1];
            int row = s0 + r0 + m * 16 + g;
            float* outp = gdst[w];
            size_t base0 = ((size_t)((b * HH + h) * SS + row)) * HD + lcol;
            size_t base1 = ((size_t)((b * HH + h) * SS + row + 8)) * HD + lcol;
            *(float2*)&outp[base0] = make_float2(cvtf(acc[m][n][0] + b0), cvtf(acc[m][n][1] + b1));
            *(float2*)&outp[base1] = make_float2(cvtf(acc[m][n][2] + b0), cvtf(acc[m][n][3] + b1));
        }
    }
}

// ============================================================================
// Kernel 2: flash attention over COMPACTED keys. grid (8, 16, 8), 128 threads,
// ~106.5KB smem -> 2 CTAs/SM. K/V rows gathered via per-batch index list;
// only ceil(nb/128) tiles processed (~4 avg instead of 8). Padding columns
// (j >= nb) zeroed via inline compare (no mask smem).
// ============================================================================
#define PA  68
#define AO_K 0
#define AO_V (128 * PA)
#define AO_Q (2 * 128 * PA)
#define AO_IDX (3 * 128 * PA)          // uint16[1024] = 512 float slots
#define ATTN_F (AO_IDX + 512)
#define EXPC 0.18033688f   // 0.125 * log2(e)

static __device__ __forceinline__ void s_half(float p[2][8][4], const float* Qs,
                                              const float* Ks, int r0, int n0,
                                              int g, int t) {
    #pragma unroll
    for (int m = 0; m < 2; ++m)
        #pragma unroll
        for (int n = 0; n < 8; ++n)
            #pragma unroll
            for (int j = 0; j < 4; ++j) p[m][n][j] = 0.f;
    #pragma unroll
    for (int kk = 0; kk < 8; ++kk) {
        uint32_t a0[4], a1[4];
        lda(a0, Qs, PA, r0, kk * 8, g, t);
        lda(a1, Qs, PA, r0 + 16, kk * 8, g, t);
        #pragma unroll
        for (int n = 0; n < 8; ++n) {
            uint32_t bb[2];
            ldb_nk(bb, Ks, PA, n0 + n * 8, kk * 8, g, t);
            mma8(p[0][n], a0, bb);
            mma8(p[1][n], a1, bb);
        }
    }
}

// colbase = global compacted-column index of this half's col 0.
static __device__ __forceinline__ void exp_half(float p[2][8][4], int colbase, int nb,
                                                float rs[2][2], int t) {
    #pragma unroll
    for (int m = 0; m < 2; ++m)
        #pragma unroll
        for (int n = 0; n < 8; ++n) {
            int col = colbase + n * 8 + t * 2;
            float mx = (col < nb) ? 1.f : 0.f;
            float my = (col + 1 < nb) ? 1.f : 0.f;
            p[m][n][0] = ex2f(p[m][n][0] * EXPC) * mx;
            p[m][n][1] = ex2f(p[m][n][1] * EXPC) * my;
            p[m][n][2] = ex2f(p[m][n][2] * EXPC) * mx;
            p[m][n][3] = ex2f(p[m][n][3] * EXPC) * my;
            rs[m][0] += p[m][n][0] + p[m][n][1];
            rs[m][1] += p[m][n][2] + p[m][n][3];
        }
}

static __device__ __forceinline__ void pv_half(float o[2][8][4], const float p[2][8][4],
                                               const float* Vs, int n0, int g, int t) {
    #pragma unroll
    for (int kkp = 0; kkp < 8; ++kkp) {
        uint32_t A0[4] = { __float_as_uint(p[0][kkp][0]), __float_as_uint(p[0][kkp][2]),
                           __float_as_uint(p[0][kkp][1]), __float_as_uint(p[0][kkp][3]) };
        uint32_t A1[4] = { __float_as_uint(p[1][kkp][0]), __float_as_uint(p[1][kkp][2]),
                           __float_as_uint(p[1][kkp][1]), __float_as_uint(p[1][kkp][3]) };
        const float* vrow0 = Vs + (n0 + kkp * 8 + 2 * t) * PA;
        const float* vrow1 = vrow0 + PA;
        #pragma unroll
        for (int n = 0; n < 8; ++n) {
            uint32_t bb[2];
            bb[0] = __float_as_uint(vrow0[n * 8 + g]);
            bb[1] = __float_as_uint(vrow1[n * 8 + g]);
            mma8(o[0][n], A0, bb);
            mma8(o[1][n], A1, bb);
        }
    }
}

__global__ __launch_bounds__(128, 2) void attn_mma()
{
    extern __shared__ float sm[];
    float* Ks = sm + AO_K;
    float* Vs = sm + AO_V;
    float* Qs = sm + AO_Q;
    unsigned short* s_idx = (unsigned short*)(sm + AO_IDX);
    const uint32_t sb = smem_u32(sm);

    const int b = blockIdx.z, h = blockIdx.y, q0 = blockIdx.x * 128;
    const int tid = threadIdx.x, wid = tid >> 5, lane = tid & 31;
    const int g = lane >> 2, t = lane & 3;
    const int r0 = wid * 32;

    const size_t bh = (size_t)(b * HH + h) * SS * HD;
    const float* Qp = g_Q + bh;
    const float* Kp = g_K + bh;
    const float* Vp = g_V + bh;

    // indices + count first (cp.async sources depend on them)
    for (int i = tid; i < SS; i += 128)
        s_idx[i] = (unsigned short)g_idx[b * SS + i];
    const int nb = g_nb[b];
    const int ntiles = (nb + 127) >> 7;
    __syncthreads();

    // prologue: gathered K(0) | gathered V(0) + Q
    for (int i = tid; i < 128 * 16; i += 128) {
        int r = i >> 4, c4 = (i & 15) << 2;
        int src = s_idx[r];
        cpa16(sb + (uint32_t)(AO_K + r * PA + c4) * 4, &Kp[(size_t)src * HD + c4]);
    }
    CP_COMMIT();
    for (int i = tid; i < 128 * 16; i += 128) {
        int r = i >> 4, c4 = (i & 15) << 2;
        int src = s_idx[r];
        cpa16(sb + (uint32_t)(AO_V + r * PA + c4) * 4, &Vp[(size_t)src * HD + c4]);
        cpa16(sb + (uint32_t)(AO_Q + r * PA + c4) * 4, &Qp[(size_t)(q0 + r) * HD + c4]);
    }
    CP_COMMIT();
    CP_WAIT(0);
    __syncthreads();

    float o[2][8][4] = {};
    float rs[2][2] = {};
    float p[2][8][4];

    for (int kt = 0; kt < ntiles; ++kt) {
        CP_WAIT(1);           // K(kt) ready; no-op at kt=0
        __syncthreads();

        // half 0: compacted keys [kt*128, kt*128+64)
        s_half(p, Qs, Ks, r0, 0, g, t);
        exp_half(p, kt * 128, nb, rs, t);
        CP_WAIT(0);           // V(kt) ready
        __syncthreads();
        pv_half(o, p, Vs, 0, g, t);

        // half 1: compacted keys [kt*128+64, kt*128+128)
        s_half(p, Qs, Ks, r0, 64, g, t);
        exp_half(p, kt * 128 + 64, nb, rs, t);
        __syncthreads();      // all warps done reading Ks
        if (kt + 1 < ntiles) {
            for (int i = tid; i < 128 * 16; i += 128) {
                int r = i >> 4, c4 = (i & 15) << 2;
                int src = s_idx[(kt + 1) * 128 + r];
                cpa16(sb + (uint32_t)(AO_K + r * PA + c4) * 4,
                      &Kp[(size_t)src * HD + c4]);
            }
        }
        CP_COMMIT();          // group: K(kt+1) (empty on last tile)
        pv_half(o, p, Vs, 64, g, t);
        __syncthreads();      // all warps done reading Vs
        if (kt + 1 < ntiles) {
            for (int i = tid; i < 128 * 16; i += 128) {
                int r = i >> 4, c4 = (i & 15) << 2;
                int src = s_idx[(kt + 1) * 128 + r];
                cpa16(sb + (uint32_t)(AO_V + r * PA + c4) * 4,
                      &Vp[(size_t)src * HD + c4]);
            }
        }
        CP_COMMIT();          // group: V(kt+1) (empty on last tile)
    }

    #pragma unroll
    for (int m = 0; m < 2; ++m)
        #pragma unroll
        for (int j = 0; j < 2; ++j) {
            rs[m][j] += __shfl_xor_sync(0xffffffffu, rs[m][j], 1);
            rs[m][j] += __shfl_xor_sync(0xffffffffu, rs[m][j], 2);
        }

    #pragma unroll
    for (int m = 0; m < 2; ++m) {
        const float inv0 = 1.0f / rs[m][0], inv1 = 1.0f / rs[m][1];
        const int row = q0 + r0 + m * 16 + g;
        #pragma unroll
        for (int n = 0; n < 8; ++n) {
            int col = n * 8 + t * 2;
            size_t base0 = ((size_t)(b * SS + row)) * DD + h * HD + col;
            size_t base1 = ((size_t)(b * SS + row + 8)) * DD + h * HD + col;
            *(float2*)&g_C[base0] = make_float2(cvtf(o[m][n][0] * inv0), cvtf(o[m][n][1] * inv0));
            *(float2*)&g_C[base1] = make_float2(cvtf(o[m][n][2] * inv1), cvtf(o[m][n][3] * inv1));
        }
    }
}

// ============================================================================
// Kernel 3: out-proj Y = C @ Wo^T + bo (R8-identical). grid (8, 64), 256 thr.
// Block 128x128, warp 32x64, cp.async double-buffered k-chunks of 32.
// ============================================================================
#define PO 36
#define OB_STRIDE (2 * 128 * PO)

__global__ __launch_bounds__(256, 2) void outproj_mma(
    const float* __restrict__ bo, float* __restrict__ y)
{
    extern __shared__ float sm[];
    const uint32_t sb = smem_u32(sm);

    const int n0 = blockIdx.x * 128;
    const int m0 = blockIdx.y * 128;
    const int tid = threadIdx.x, wid = tid >> 5, lane = tid & 31;
    const int g = lane >> 2, t = lane & 3;
    const int wr = wid & 3, wc = wid >> 2;
    const int r0 = wr * 32, c0 = wc * 64;

    auto issue = [&](int ch, int buf) {
        const uint32_t bofs = (uint32_t)(buf * OB_STRIDE);
        for (int i = tid; i < 128 * 8; i += 256) {
            int r = i >> 3, c4 = (i & 7) << 2;
            cpa16(sb + (bofs + (uint32_t)(r * PO + c4)) * 4,
                  &g_C[(size_t)(m0 + r) * DD + ch * 32 + c4]);
            cpa16(sb + (bofs + (uint32_t)(128 * PO + r * PO + c4)) * 4,
                  &g_Wo[(size_t)(n0 + r) * DD + ch * 32 + c4]);
        }
        CP_COMMIT();
    };
    issue(0, 0);
    issue(1, 1);

    float acc[2][8][4] = {};
    for (int ch = 0; ch < 32; ++ch) {
        CP_WAIT(1);
        __syncthreads();
        const float* Cs = sm + (ch & 1) * OB_STRIDE;
        const float* Ws = Cs + 128 * PO;
        #pragma unroll
        for (int kk = 0; kk < 4; ++kk) {
            uint32_t a0[4], a1[4];
            lda(a0, Cs, PO, r0, kk * 8, g, t);
            lda(a1, Cs, PO, r0 + 16, kk * 8, g, t);
            #pragma unroll
            for (int n = 0; n < 8; ++n) {
                uint32_t bb[2];
                ldb_nk(bb, Ws, PO, c0 + n * 8, kk * 8, g, t);
                mma8(acc[0][n], a0, bb);
                mma8(acc[1][n], a1, bb);
            }
        }
        __syncthreads();
        if (ch + 2 < 32) issue(ch + 2, ch & 1);
        else CP_COMMIT();
    }

    #pragma unroll
    for (int m = 0; m < 2; ++m) {
        #pragma unroll
        for (int n = 0; n < 8; ++n) {
            int col = c0 + n * 8 + t * 2;
            float b0 = bo[n0 + col], b1 = bo[n0 + col + 1];
            int row = m0 + r0 + m * 16 + g;
            size_t base0 = (size_t)row * DD + n0 + col;
            size_t base1 = (size_t)(row + 8) * DD + n0 + col;
            *(float2*)&y[base0] = make_float2(acc[m][n][0] + b0, acc[m][n][1] + b1);
            *(float2*)&y[base1] = make_float2(acc[m][n][2] + b0, acc[m][n][3] + b1);
        }
    }
}

// ============================================================================
extern "C" void kernel_launch(void* const* d_in, const int* in_sizes, int n_in,
                              void* d_out, int out_size)
{
    const float* x  = (const float*)d_in[0];
    const int* mk   = (const int*)d_in[1];
    const float* Wq = (const float*)d_in[2];
    const float* bq = (const float*)d_in[3];
    const float* Wk = (const float*)d_in[4];
    const float* bk = (const float*)d_in[5];
    const float* Wv = (const float*)d_in[6];
    const float* bv = (const float*)d_in[7];
    const float* Wo = (const float*)d_in[8];
    const float* bo = (const float*)d_in[9];
    float* y = (float*)d_out;

    const int smem_proj = PRJ_SMEM_F * 4;     // ~88 KB
    const int smem_attn = ATTN_F * 4;         // ~106.5 KB -> 2 CTAs/SM
    const int smem_out  = 2 * OB_STRIDE * 4;  // ~74 KB -> 2 CTAs/SM
    cudaFuncSetAttribute(proj_mma, cudaFuncAttributeMaxDynamicSharedMemorySize, smem_proj);
    cudaFuncSetAttribute(attn_mma, cudaFuncAttributeMaxDynamicSharedMemorySize, smem_attn);
    cudaFuncSetAttribute(outproj_mma, cudaFuncAttributeMaxDynamicSharedMemorySize, smem_out);

    round_wo<<<DD * DD / 1024, 256>>>(Wo);
    build_idx<<<BB, SS>>>(mk);
    proj_mma<<<dim3(SS / 128, HH, BB), 512, smem_proj>>>(x, Wq, bq, Wk, bk, Wv, bv);
    attn_mma<<<dim3(SS / 128, HH, BB), 128, smem_attn>>>();
    outproj_mma<<<dim3(DD / 128, BB * SS / 128), 256, smem_out>>>(bo, y);
}

// round 12
// speedup vs baseline: 1.5016x; 1.0315x over previous
#include <cuda_runtime.h>
#include <cstdint>

#define BB 8
#define SS 1024
#define DD 1024
#define HH 16
#define HD 64

// Scratch (device globals). All contents tf32-rounded fp32 (rounded once, rna).
__device__ float g_Q[BB*HH*SS*HD];
__device__ float g_K[BB*HH*SS*HD];
__device__ float g_V[BB*HH*SS*HD];
__device__ float g_C[(size_t)BB*SS*DD];
__device__ float g_Wo[DD*DD];
__device__ int   g_idx[BB*SS];   // per-batch compacted unmasked key indices
__device__ int   g_nb[BB];       // per-batch unmasked count

// ---------------- helpers ----------------
static __device__ __forceinline__ uint32_t cvt_tf32(float f) {
    uint32_t u; asm("cvt.rna.tf32.f32 %0, %1;" : "=r"(u) : "f"(f)); return u;
}
static __device__ __forceinline__ float cvtf(float f) { return __uint_as_float(cvt_tf32(f)); }
static __device__ __forceinline__ float ex2f(float x) {
    float y; asm("ex2.approx.f32 %0, %1;" : "=f"(y) : "f"(x)); return y;
}
static __device__ __forceinline__ void mma8(float* d, const uint32_t* a, const uint32_t* b) {
    asm volatile("mma.sync.aligned.m16n8k8.row.col.f32.tf32.tf32.f32 "
        "{%0,%1,%2,%3}, {%4,%5,%6,%7}, {%8,%9}, {%0,%1,%2,%3};"
        : "+f"(d[0]), "+f"(d[1]), "+f"(d[2]), "+f"(d[3])
        : "r"(a[0]), "r"(a[1]), "r"(a[2]), "r"(a[3]), "r"(b[0]), "r"(b[1]));
}
static __device__ __forceinline__ void lda(uint32_t* a, const float* s, int P,
                                           int r0, int k0, int g, int t) {
    a[0] = __float_as_uint(s[(r0 + g) * P + k0 + t]);
    a[1] = __float_as_uint(s[(r0 + g + 8) * P + k0 + t]);
    a[2] = __float_as_uint(s[(r0 + g) * P + k0 + t + 4]);
    a[3] = __float_as_uint(s[(r0 + g + 8) * P + k0 + t + 4]);
}
static __device__ __forceinline__ void ldb_nk(uint32_t* b, const float* s, int P,
                                              int n0, int k0, int g, int t) {
    b[0] = __float_as_uint(s[(n0 + g) * P + k0 + t]);
    b[1] = __float_as_uint(s[(n0 + g) * P + k0 + t + 4]);
}
static __device__ __forceinline__ uint32_t smem_u32(const void* p) {
    uint32_t a;
    asm("{ .reg .u64 t; cvta.to.shared.u64 t, %1; cvt.u32.u64 %0, t; }" : "=r"(a) : "l"(p));
    return a;
}
static __device__ __forceinline__ void cpa16(uint32_t dst, const void* src) {
    asm volatile("cp.async.ca.shared.global [%0], [%1], 16;" :: "r"(dst), "l"(src));
}
#define CP_COMMIT() asm volatile("cp.async.commit_group;" ::: "memory")
#define CP_WAIT(n)  asm volatile("cp.async.wait_group %0;" :: "n"(n) : "memory")

// ============================================================================
// Kernel 0a: tf32-round Wo (once).
// ============================================================================
__global__ void round_wo(const float* __restrict__ Wo) {
    int i = (blockIdx.x * 256 + threadIdx.x) * 4;
    float4 v = *(const float4*)&Wo[i];
    *(float4*)&g_Wo[i] = make_float4(cvtf(v.x), cvtf(v.y), cvtf(v.z), cvtf(v.w));
}

// ============================================================================
// Kernel 0b: per-batch key compaction (sorted unmasked indices + count).
// ============================================================================
__global__ void build_idx(const int* __restrict__ mask) {
    __shared__ int wsum[33];
    const int b = blockIdx.x, tid = threadIdx.x;
    const int lane = tid & 31, w = tid >> 5;
    const int flag = mask[b * SS + tid] ? 0 : 1;   // 1 = unmasked (keep)
    unsigned bal = __ballot_sync(0xffffffffu, flag);
    int pre = __popc(bal & ((1u << lane) - 1u));
    if (lane == 0) wsum[w] = __popc(bal);
    __syncthreads();
    if (tid == 0) {
        int s = 0;
        for (int i = 0; i < 32; ++i) { int tt = wsum[i]; wsum[i] = s; s += tt; }
        wsum[32] = s;
        g_nb[b] = s;
    }
    __syncthreads();
    const int nb = wsum[32];
    if (tid >= nb) g_idx[b * SS + tid] = 0;          // pad slots -> row 0 (zeroed later)
    if (flag) g_idx[b * SS + wsum[w] + pre] = tid;   // distinct slots (< nb)
}

// ============================================================================
// Kernel 1: fused QKV projection (R8-identical). grid (8, 16, 8), 512 threads.
// ============================================================================
#define PP 68
#define PRJ_WS   (128 * PP)
#define PRJ_BIAS (128 * PP + 192 * PP)
#define PRJ_SMEM_F (PRJ_BIAS + 192)

__global__ __launch_bounds__(512) void proj_mma(
    const float* __restrict__ x,
    const float* __restrict__ Wq, const float* __restrict__ bq,
    const float* __restrict__ Wk, const float* __restrict__ bk,
    const float* __restrict__ Wv, const float* __restrict__ bv)
{
    extern __shared__ float sm[];
    float* xs = sm;
    float* ws = sm + PRJ_WS;
    float* sbias = sm + PRJ_BIAS;
    const uint32_t sb = smem_u32(sm);

    const int b = blockIdx.z, h = blockIdx.y, s0 = blockIdx.x * 128;
    const int tid = threadIdx.x, wid = tid >> 5, lane = tid & 31;
    const int g = lane >> 2, t = lane & 3;
    const int wr = wid & 3, wc = wid >> 2;
    const int r0 = wr * 32, c0 = wc * 48;

    for (int i = tid; i < 128 * 16; i += 512) {
        int r = i >> 4, c4 = (i & 15) << 2;
        cpa16(sb + (uint32_t)(r * PP + c4) * 4,
              &x[((size_t)(b * SS + s0 + r)) * DD + h * HD + c4]);
    }
    CP_COMMIT();

    {
        const float* Wsrc[3] = { Wq + (size_t)h * HD * HD, Wk + (size_t)h * HD * HD,
                                 Wv + (size_t)h * HD * HD };
        for (int i = tid; i < 3 * 4096; i += 512) {
            int w = i >> 12, r = i & 4095, d = r >> 6, e = r & 63;
            ws[(w * 64 + e) * PP + d] = cvtf(Wsrc[w][r]);
        }
        if (tid < 192) {
            int w = tid >> 6, e = tid & 63;
            const float* bsrc[3] = { bq, bk, bv };
            sbias[tid] = bsrc[w][h * HD + e];
        }
    }
    CP_WAIT(0);
    __syncthreads();
    for (int i = tid; i < 128 * 16; i += 512) {
        int r = i >> 4, c4 = (i & 15) << 2;
        float4 v = *(float4*)&xs[r * PP + c4];
        *(float4*)&xs[r * PP + c4] = make_float4(cvtf(v.x), cvtf(v.y), cvtf(v.z), cvtf(v.w));
    }
    __syncthreads();

    float acc[2][6][4] = {};
    #pragma unroll
    for (int kk = 0; kk < 8; ++kk) {
        uint32_t a0[4], a1[4];
        lda(a0, xs, PP, r0, kk * 8, g, t);
        lda(a1, xs, PP, r0 + 16, kk * 8, g, t);
        #pragma unroll
        for (int n = 0; n < 6; ++n) {
            uint32_t bb[2];
            ldb_nk(bb, ws, PP, c0 + n * 8, kk * 8, g, t);
            mma8(acc[0][n], a0, bb);
            mma8(acc[1][n], a1, bb);
        }
    }

    float* gdst[3] = { g_Q, g_K, g_V };
    #pragma unroll
    for (int m = 0; m < 2; ++m) {
        #pragma unroll
        for (int n = 0; n < 6; ++n) {
            int gcol = c0 + n * 8 + t * 2;
            int w = gcol >> 6, lcol = gcol & 63;
            float b0 = sbias[gcol], b1 = sbias[gcol + 1];
            int row = s0 + r0 + m * 16 + g;
            float* outp = gdst[w];
            size_t base0 = ((size_t)((b * HH + h) * SS + row)) * HD + lcol;
            size_t base1 = ((size_t)((b * HH + h) * SS + row + 8)) * HD + lcol;
            *(float2*)&outp[base0] = make_float2(cvtf(acc[m][n][0] + b0), cvtf(acc[m][n][1] + b1));
            *(float2*)&outp[base1] = make_float2(cvtf(acc[m][n][2] + b0), cvtf(acc[m][n][3] + b1));
        }
    }
}

// ============================================================================
// Kernel 2: flash attention over COMPACTED keys (R11-identical).
// grid (8, 16, 8), 128 threads, ~106.5KB smem -> 2 CTAs/SM.
// ============================================================================
#define PA  68
#define AO_K 0
#define AO_V (128 * PA)
#define AO_Q (2 * 128 * PA)
#define AO_IDX (3 * 128 * PA)          // uint16[1024] = 512 float slots
#define ATTN_F (AO_IDX + 512)
#define EXPC 0.18033688f   // 0.125 * log2(e)

static __device__ __forceinline__ void s_half(float p[2][8][4], const float* Qs,
                                              const float* Ks, int r0, int n0,
                                              int g, int t) {
    #pragma unroll
    for (int m = 0; m < 2; ++m)
        #pragma unroll
        for (int n = 0; n < 8; ++n)
            #pragma unroll
            for (int j = 0; j < 4; ++j) p[m][n][j] = 0.f;
    #pragma unroll
    for (int kk = 0; kk < 8; ++kk) {
        uint32_t a0[4], a1[4];
        lda(a0, Qs, PA, r0, kk * 8, g, t);
        lda(a1, Qs, PA, r0 + 16, kk * 8, g, t);
        #pragma unroll
        for (int n = 0; n < 8; ++n) {
            uint32_t bb[2];
            ldb_nk(bb, Ks, PA, n0 + n * 8, kk * 8, g, t);
            mma8(p[0][n], a0, bb);
            mma8(p[1][n], a1, bb);
        }
    }
}

static __device__ __forceinline__ void exp_half(float p[2][8][4], int colbase, int nb,
                                                float rs[2][2], int t) {
    #pragma unroll
    for (int m = 0; m < 2; ++m)
        #pragma unroll
        for (int n = 0; n < 8; ++n) {
            int col = colbase + n * 8 + t * 2;
            float mx = (col < nb) ? 1.f : 0.f;
            float my = (col + 1 < nb) ? 1.f : 0.f;
            p[m][n][0] = ex2f(p[m][n][0] * EXPC) * mx;
            p[m][n][1] = ex2f(p[m][n][1] * EXPC) * my;
            p[m][n][2] = ex2f(p[m][n][2] * EXPC) * mx;
            p[m][n][3] = ex2f(p[m][n][3] * EXPC) * my;
            rs[m][0] += p[m][n][0] + p[m][n][1];
            rs[m][1] += p[m][n][2] + p[m][n][3];
        }
}

static __device__ __forceinline__ void pv_half(float o[2][8][4], const float p[2][8][4],
                                               const float* Vs, int n0, int g, int t) {
    #pragma unroll
    for (int kkp = 0; kkp < 8; ++kkp) {
        uint32_t A0[4] = { __float_as_uint(p[0][kkp][0]), __float_as_uint(p[0][kkp][2]),
                           __float_as_uint(p[0][kkp][1]), __float_as_uint(p[0][kkp][3]) };
        uint32_t A1[4] = { __float_as_uint(p[1][kkp][0]), __float_as_uint(p[1][kkp][2]),
                           __float_as_uint(p[1][kkp][1]), __float_as_uint(p[1][kkp][3]) };
        const float* vrow0 = Vs + (n0 + kkp * 8 + 2 * t) * PA;
        const float* vrow1 = vrow0 + PA;
        #pragma unroll
        for (int n = 0; n < 8; ++n) {
            uint32_t bb[2];
            bb[0] = __float_as_uint(vrow0[n * 8 + g]);
            bb[1] = __float_as_uint(vrow1[n * 8 + g]);
            mma8(o[0][n], A0, bb);
            mma8(o[1][n], A1, bb);
        }
    }
}

__global__ __launch_bounds__(128, 2) void attn_mma()
{
    extern __shared__ float sm[];
    float* Ks = sm + AO_K;
    float* Vs = sm + AO_V;
    float* Qs = sm + AO_Q;
    unsigned short* s_idx = (unsigned short*)(sm + AO_IDX);
    const uint32_t sb = smem_u32(sm);

    const int b = blockIdx.z, h = blockIdx.y, q0 = blockIdx.x * 128;
    const int tid = threadIdx.x, wid = tid >> 5, lane = tid & 31;
    const int g = lane >> 2, t = lane & 3;
    const int r0 = wid * 32;

    const size_t bh = (size_t)(b * HH + h) * SS * HD;
    const float* Qp = g_Q + bh;
    const float* Kp = g_K + bh;
    const float* Vp = g_V + bh;

    for (int i = tid; i < SS; i += 128)
        s_idx[i] = (unsigned short)g_idx[b * SS + i];
    const int nb = g_nb[b];
    const int ntiles = (nb + 127) >> 7;
    __syncthreads();

    for (int i = tid; i < 128 * 16; i += 128) {
        int r = i >> 4, c4 = (i & 15) << 2;
        int src = s_idx[r];
        cpa16(sb + (uint32_t)(AO_K + r * PA + c4) * 4, &Kp[(size_t)src * HD + c4]);
    }
    CP_COMMIT();
    for (int i = tid; i < 128 * 16; i += 128) {
        int r = i >> 4, c4 = (i & 15) << 2;
        int src = s_idx[r];
        cpa16(sb + (uint32_t)(AO_V + r * PA + c4) * 4, &Vp[(size_t)src * HD + c4]);
        cpa16(sb + (uint32_t)(AO_Q + r * PA + c4) * 4, &Qp[(size_t)(q0 + r) * HD + c4]);
    }
    CP_COMMIT();
    CP_WAIT(0);
    __syncthreads();

    float o[2][8][4] = {};
    float rs[2][2] = {};
    float p[2][8][4];

    for (int kt = 0; kt < ntiles; ++kt) {
        CP_WAIT(1);
        __syncthreads();

        s_half(p, Qs, Ks, r0, 0, g, t);
        exp_half(p, kt * 128, nb, rs, t);
        CP_WAIT(0);
        __syncthreads();
        pv_half(o, p, Vs, 0, g, t);

        s_half(p, Qs, Ks, r0, 64, g, t);
        exp_half(p, kt * 128 + 64, nb, rs, t);
        __syncthreads();
        if (kt + 1 < ntiles) {
            for (int i = tid; i < 128 * 16; i += 128) {
                int r = i >> 4, c4 = (i & 15) << 2;
                int src = s_idx[(kt + 1) * 128 + r];
                cpa16(sb + (uint32_t)(AO_K + r * PA + c4) * 4,
                      &Kp[(size_t)src * HD + c4]);
            }
        }
        CP_COMMIT();
        pv_half(o, p, Vs, 64, g, t);
        __syncthreads();
        if (kt + 1 < ntiles) {
            for (int i = tid; i < 128 * 16; i += 128) {
                int r = i >> 4, c4 = (i & 15) << 2;
                int src = s_idx[(kt + 1) * 128 + r];
                cpa16(sb + (uint32_t)(AO_V + r * PA + c4) * 4,
                      &Vp[(size_t)src * HD + c4]);
            }
        }
        CP_COMMIT();
    }

    #pragma unroll
    for (int m = 0; m < 2; ++m)
        #pragma unroll
        for (int j = 0; j < 2; ++j) {
            rs[m][j] += __shfl_xor_sync(0xffffffffu, rs[m][j], 1);
            rs[m][j] += __shfl_xor_sync(0xffffffffu, rs[m][j], 2);
        }

    #pragma unroll
    for (int m = 0; m < 2; ++m) {
        const float inv0 = 1.0f / rs[m][0], inv1 = 1.0f / rs[m][1];
        const int row = q0 + r0 + m * 16 + g;
        #pragma unroll
        for (int n = 0; n < 8; ++n) {
            int col = n * 8 + t * 2;
            size_t base0 = ((size_t)(b * SS + row)) * DD + h * HD + col;
            size_t base1 = ((size_t)(b * SS + row + 8)) * DD + h * HD + col;
            *(float2*)&g_C[base0] = make_float2(cvtf(o[m][n][0] * inv0), cvtf(o[m][n][1] * inv0));
            *(float2*)&g_C[base1] = make_float2(cvtf(o[m][n][2] * inv1), cvtf(o[m][n][3] * inv1));
        }
    }
}

// ============================================================================
// Kernel 3: out-proj Y = C @ Wo^T + bo. grid (8, 64), 128 threads (4 warps).
// Block 128x128, warp 64x64 (2x2) -> 1.0 LDS/mma. cp.async double-buffered
// k-chunks of 32 (74KB smem, ~200 regs -> 2 CTAs/SM).
// ============================================================================
#define PO 36
#define OB_STRIDE (2 * 128 * PO)

__global__ __launch_bounds__(128, 2) void outproj_mma(
    const float* __restrict__ bo, float* __restrict__ y)
{
    extern __shared__ float sm[];
    const uint32_t sb = smem_u32(sm);

    const int n0 = blockIdx.x * 128;
    const int m0 = blockIdx.y * 128;
    const int tid = threadIdx.x, wid = tid >> 5, lane = tid & 31;
    const int g = lane >> 2, t = lane & 3;
    const int wr = wid & 1, wc = wid >> 1;
    const int r0 = wr * 64, c0 = wc * 64;

    auto issue = [&](int ch, int buf) {
        const uint32_t bofs = (uint32_t)(buf * OB_STRIDE);
        for (int i = tid; i < 128 * 8; i += 128) {
            int r = i >> 3, c4 = (i & 7) << 2;
            cpa16(sb + (bofs + (uint32_t)(r * PO + c4)) * 4,
                  &g_C[(size_t)(m0 + r) * DD + ch * 32 + c4]);
            cpa16(sb + (bofs + (uint32_t)(128 * PO + r * PO + c4)) * 4,
                  &g_Wo[(size_t)(n0 + r) * DD + ch * 32 + c4]);
        }
        CP_COMMIT();
    };
    issue(0, 0);
    issue(1, 1);

    float acc[4][8][4] = {};
    for (int ch = 0; ch < 32; ++ch) {
        CP_WAIT(1);
        __syncthreads();
        const float* Cs = sm + (ch & 1) * OB_STRIDE;
        const float* Ws = Cs + 128 * PO;
        #pragma unroll
        for (int kk = 0; kk < 4; ++kk) {
            uint32_t a_[4][4];
            #pragma unroll
            for (int m = 0; m < 4; ++m)
                lda(a_[m], Cs, PO, r0 + m * 16, kk * 8, g, t);
            #pragma unroll
            for (int n = 0; n < 8; ++n) {
                uint32_t bb[2];
                ldb_nk(bb, Ws, PO, c0 + n * 8, kk * 8, g, t);
                #pragma unroll
                for (int m = 0; m < 4; ++m)
                    mma8(acc[m][n], a_[m], bb);
            }
        }
        __syncthreads();
        if (ch + 2 < 32) issue(ch + 2, ch & 1);
        else CP_COMMIT();
    }

    #pragma unroll
    for (int m = 0; m < 4; ++m) {
        #pragma unroll
        for (int n = 0; n < 8; ++n) {
            int col = c0 + n * 8 + t * 2;
            float b0 = bo[n0 + col], b1 = bo[n0 + col + 1];
            int row = m0 + r0 + m * 16 + g;
            size_t base0 = (size_t)row * DD + n0 + col;
            size_t base1 = (size_t)(row + 8) * DD + n0 + col;
            *(float2*)&y[base0] = make_float2(acc[m][n][0] + b0, acc[m][n][1] + b1);
            *(float2*)&y[base1] = make_float2(acc[m][n][2] + b0, acc[m][n][3] + b1);
        }
    }
}

// ============================================================================
extern "C" void kernel_launch(void* const* d_in, const int* in_sizes, int n_in,
                              void* d_out, int out_size)
{
    const float* x  = (const float*)d_in[0];
    const int* mk   = (const int*)d_in[1];
    const float* Wq = (const float*)d_in[2];
    const float* bq = (const float*)d_in[3];
    const float* Wk = (const float*)d_in[4];
    const float* bk = (const float*)d_in[5];
    const float* Wv = (const float*)d_in[6];
    const float* bv = (const float*)d_in[7];
    const float* Wo = (const float*)d_in[8];
    const float* bo = (const float*)d_in[9];
    float* y = (float*)d_out;

    const int smem_proj = PRJ_SMEM_F * 4;     // ~88 KB
    const int smem_attn = ATTN_F * 4;         // ~106.5 KB -> 2 CTAs/SM
    const int smem_out  = 2 * OB_STRIDE * 4;  // ~74 KB -> 2 CTAs/SM
    cudaFuncSetAttribute(proj_mma, cudaFuncAttributeMaxDynamicSharedMemorySize, smem_proj);
    cudaFuncSetAttribute(attn_mma, cudaFuncAttributeMaxDynamicSharedMemorySize, smem_attn);
    cudaFuncSetAttribute(outproj_mma, cudaFuncAttributeMaxDynamicSharedMemorySize, smem_out);

    round_wo<<<DD * DD / 1024, 256>>>(Wo);
    build_idx<<<BB, SS>>>(mk);
    proj_mma<<<dim3(SS / 128, HH, BB), 512, smem_proj>>>(x, Wq, bq, Wk, bk, Wv, bv);
    attn_mma<<<dim3(SS / 128, HH, BB), 128, smem_attn>>>();
    outproj_mma<<<dim3(DD / 128, BB * SS / 128), 128, smem_out>>>(bo, y);
}